// round 10
// baseline (speedup 1.0000x reference)
#include <cuda_runtime.h>
#include <cuda_bf16.h>
#include <math.h>
#include <limits.h>

// Problem constants (fixed by the reference)
#define N_NODES    12288
#define N_FEATURES 256
#define KEY_DIM    128
#define N_GRAPHS   192
#define QKV_COLS   512        // [Q(128) | K(128) | V(256)]

#define SPLIT 4               // row-split CTAs per graph for the score phase
#define NGMAX 128
#define KPAD  132             // 132*4B = 528B row stride: 16B-aligned, phase-conflict-free

typedef unsigned long long ull;

// Packed fp32x2 ops (Blackwell sm_103a; ptxas never emits FFMA2 from C++)
__device__ __forceinline__ void ffma2(ull& d, ull a, ull b) {
    asm("fma.rn.f32x2 %0, %1, %2, %0;" : "+l"(d) : "l"(a), "l"(b));
}
__device__ __forceinline__ ull pack2(float lo, float hi) {
    ull r; asm("mov.b64 %0, {%1, %2};" : "=l"(r) : "f"(lo), "f"(hi)); return r;
}
__device__ __forceinline__ float2 unpack2(ull v) {
    float2 r; asm("mov.b64 {%0, %1}, %2;" : "=f"(r.x), "=f"(r.y) : "l"(v)); return r;
}
__device__ __forceinline__ ull addx2(ull a, ull b) {
    ull r; asm("add.rn.f32x2 %0, %1, %2;" : "=l"(r) : "l"(a), "l"(b)); return r;
}

// Static device scratch (no allocs)
__device__ float g_QKV[N_NODES * QKV_COLS];              // 25.2 MB
__device__ float g_wpart[SPLIT * N_GRAPHS * NGMAX];      // 384 KB partial colsums
__device__ int   g_start[N_GRAPHS];
__device__ int   g_end[N_GRAPHS];

// ---------------------------------------------------------------------------
// Kernel 0: init per-graph ranges
// ---------------------------------------------------------------------------
__global__ void init_ranges_kernel() {
    int g = blockIdx.x * blockDim.x + threadIdx.x;
    if (g < N_GRAPHS) {
        g_start[g] = INT_MAX;
        g_end[g]   = 0;
    }
}

// ---------------------------------------------------------------------------
// Kernel 1: per-graph [start, end) from sorted batch (robust to int32/int64)
// ---------------------------------------------------------------------------
__global__ void compute_ranges_kernel(const void* __restrict__ batch) {
    int i = blockIdx.x * blockDim.x + threadIdx.x;
    if (i >= N_NODES) return;
    const long long* b64 = (const long long*)batch;
    long long probe = b64[N_NODES / 4];
    bool is32 = (probe < 0) || (probe >= (long long)N_GRAPHS);
    int g = is32 ? ((const int*)batch)[i] : (int)b64[i];
    if (g < 0 || g >= N_GRAPHS) return;   // defensive
    atomicMin(&g_start[g], i);
    atomicMax(&g_end[g], i + 1);
}

// ---------------------------------------------------------------------------
// Kernel 2: fused QKV projection GEMM, fp32x2 FMAs, double-buffered smem.
//   QKV[N, 512] = X[N, 256] @ [Wq | Wk | Wv]
// BM=64, BN=128, BK=32, 256 threads, 8x4 micro-tile as 4 row-pairs of FFMA2.
// Dynamic smem: 2 x (A 32x66 + B 32x128) = 49.7 KB, one sync per K-step.
// ---------------------------------------------------------------------------
#define GB_M 64
#define GB_N 128
#define GB_K 32
#define GB_MPAD 66     // even -> 8B-aligned row-pair loads
#define GB_A_FLOATS (GB_K * GB_MPAD)
#define GB_B_FLOATS (GB_K * GB_N)
#define GB_SMEM_BYTES (2 * (GB_A_FLOATS + GB_B_FLOATS) * 4)

__global__ __launch_bounds__(256, 2)
void qkv_gemm_kernel(const float* __restrict__ X,
                     const float* __restrict__ Wq,
                     const float* __restrict__ Wk,
                     const float* __restrict__ Wv) {
    extern __shared__ float gsm[];
    float* Abuf[2] = { gsm, gsm + GB_A_FLOATS };
    float* Bbuf[2] = { gsm + 2 * GB_A_FLOATS, gsm + 2 * GB_A_FLOATS + GB_B_FLOATS };

    const int bx = blockIdx.x;   // 0..3 weight slab
    const int by = blockIdx.y;   // 0..191

    const float* W;
    int ldw, ncol0;
    if (bx == 0)      { W = Wq; ldw = KEY_DIM;    ncol0 = 0;   }
    else if (bx == 1) { W = Wk; ldw = KEY_DIM;    ncol0 = 0;   }
    else              { W = Wv; ldw = N_FEATURES; ncol0 = (bx - 2) * 128; }

    const int tid  = threadIdx.x;
    const int ty   = tid >> 5;        // 0..7   -> row group (8 rows)
    const int tx   = tid & 31;        // 0..31  -> col group (4 cols)
    const int row0 = by * GB_M;

    // Per-thread load coordinates (fixed across tiles)
    const int ar0 = tid >> 3,          ac0 = (tid & 7) << 2;          // A elem 0
    const int ar1 = (tid + 256) >> 3,  ac1 = ((tid + 256) & 7) << 2;  // A elem 1
    int br[4], bc[4];
#pragma unroll
    for (int i = 0; i < 4; i++) {
        int t = tid + i * 256;
        br[i] = t >> 5; bc[i] = (t & 31) << 2;
    }

    float4 aR[2], bR[4];
    // Prologue: tile 0
    aR[0] = *(const float4*)&X[(row0 + ar0) * N_FEATURES + ac0];
    aR[1] = *(const float4*)&X[(row0 + ar1) * N_FEATURES + ac1];
#pragma unroll
    for (int i = 0; i < 4; i++)
        bR[i] = *(const float4*)&W[br[i] * ldw + ncol0 + bc[i]];
    {
        float* As = Abuf[0]; float* Bs = Bbuf[0];
        As[(ac0 + 0) * GB_MPAD + ar0] = aR[0].x;
        As[(ac0 + 1) * GB_MPAD + ar0] = aR[0].y;
        As[(ac0 + 2) * GB_MPAD + ar0] = aR[0].z;
        As[(ac0 + 3) * GB_MPAD + ar0] = aR[0].w;
        As[(ac1 + 0) * GB_MPAD + ar1] = aR[1].x;
        As[(ac1 + 1) * GB_MPAD + ar1] = aR[1].y;
        As[(ac1 + 2) * GB_MPAD + ar1] = aR[1].z;
        As[(ac1 + 3) * GB_MPAD + ar1] = aR[1].w;
#pragma unroll
        for (int i = 0; i < 4; i++)
            *(float4*)&Bs[br[i] * GB_N + bc[i]] = bR[i];
    }
    __syncthreads();

    ull acc2[4][4];
#pragma unroll
    for (int rp = 0; rp < 4; rp++)
#pragma unroll
        for (int c = 0; c < 4; c++) acc2[rp][c] = 0ull;

    const int NT = N_FEATURES / GB_K;   // 8 tiles
    for (int t8 = 0; t8 < NT; t8++) {
        const int cur = t8 & 1;
        float* Ac = Abuf[cur];
        float* Bc = Bbuf[cur];

        if (t8 + 1 < NT) {              // issue next-tile LDGs early
            int k0 = (t8 + 1) * GB_K;
            aR[0] = *(const float4*)&X[(row0 + ar0) * N_FEATURES + k0 + ac0];
            aR[1] = *(const float4*)&X[(row0 + ar1) * N_FEATURES + k0 + ac1];
#pragma unroll
            for (int i = 0; i < 4; i++)
                bR[i] = *(const float4*)&W[(k0 + br[i]) * ldw + ncol0 + bc[i]];
        }

#pragma unroll
        for (int k = 0; k < GB_K; k++) {
            const ull* arow = (const ull*)&Ac[k * GB_MPAD + ty * 8]; // broadcast LDS.64
            ull a2[4];
#pragma unroll
            for (int rp = 0; rp < 4; rp++) a2[rp] = arow[rp];
            float4 bv = *(const float4*)&Bc[k * GB_N + tx * 4];
            ull bd[4] = { pack2(bv.x, bv.x), pack2(bv.y, bv.y),
                          pack2(bv.z, bv.z), pack2(bv.w, bv.w) };
#pragma unroll
            for (int rp = 0; rp < 4; rp++)
#pragma unroll
                for (int c = 0; c < 4; c++) ffma2(acc2[rp][c], a2[rp], bd[c]);
        }

        if (t8 + 1 < NT) {
            float* An = Abuf[1 - cur];
            float* Bn = Bbuf[1 - cur];
            An[(ac0 + 0) * GB_MPAD + ar0] = aR[0].x;
            An[(ac0 + 1) * GB_MPAD + ar0] = aR[0].y;
            An[(ac0 + 2) * GB_MPAD + ar0] = aR[0].z;
            An[(ac0 + 3) * GB_MPAD + ar0] = aR[0].w;
            An[(ac1 + 0) * GB_MPAD + ar1] = aR[1].x;
            An[(ac1 + 1) * GB_MPAD + ar1] = aR[1].y;
            An[(ac1 + 2) * GB_MPAD + ar1] = aR[1].z;
            An[(ac1 + 3) * GB_MPAD + ar1] = aR[1].w;
#pragma unroll
            for (int i = 0; i < 4; i++)
                *(float4*)&Bn[br[i] * GB_N + bc[i]] = bR[i];
            __syncthreads();
        }
    }

    const int col0 = bx * 128 + tx * 4;
#pragma unroll
    for (int rp = 0; rp < 4; rp++) {
        float2 p0 = unpack2(acc2[rp][0]);
        float2 p1 = unpack2(acc2[rp][1]);
        float2 p2 = unpack2(acc2[rp][2]);
        float2 p3 = unpack2(acc2[rp][3]);
        int re = row0 + ty * 8 + 2 * rp;
        *(float4*)&g_QKV[re * QKV_COLS + col0]       = make_float4(p0.x, p1.x, p2.x, p3.x);
        *(float4*)&g_QKV[(re + 1) * QKV_COLS + col0] = make_float4(p0.y, p1.y, p2.y, p3.y);
    }
}

// ---------------------------------------------------------------------------
// Kernel 3: score phase, row-split across SPLIT CTAs per graph.
// __launch_bounds__(256, 2): cap regs at 128 so 2 CTAs/SM are resident.
// LDS.128 dot loads (ulonglong2), moderate unroll to keep live regs low.
// ---------------------------------------------------------------------------
#define SC_SMEM_FLOATS (NGMAX * KPAD + 8 * NGMAX + 8 * KEY_DIM)
#define SC_SMEM_BYTES  (SC_SMEM_FLOATS * 4)

__global__ __launch_bounds__(256, 2)
void attn_score_kernel() {
    extern __shared__ float sm[];
    float* sK   = sm;                         // NGMAX * KPAD (16B-aligned rows)
    float* wcol = sK + NGMAX * KPAD;          // 8 * NGMAX (per-warp partials)
    float* sQ   = wcol + 8 * NGMAX;           // 8 * 128

    const int r    = blockIdx.x;              // 0..SPLIT-1
    const int g    = blockIdx.y;              // 0..191
    const int tid  = threadIdx.x;
    const int w    = tid >> 5;
    const int lane = tid & 31;
    const int gw   = r * 8 + w;               // 0..31 global warp within graph

    int s = g_start[g];
    int n = g_end[g] - s;
    if (n <= 0) return;                       // out kernel writes zeros
    if (n > NGMAX) n = NGMAX;                 // unreachable (mean 64, max ~95)

    // Stage K rows: float4 gmem reads, float4 smem stores (rows 16B-aligned)
    for (int t = tid; t < n * (KEY_DIM / 4); t += 256) {
        int j = t >> 5;
        int k = (t & 31) << 2;
        float4 v = *(const float4*)&g_QKV[(s + j) * QKV_COLS + KEY_DIM + k];
        *(float4*)&sK[j * KPAD + k] = v;
    }
    for (int t = tid; t < 8 * NGMAX; t += 256) wcol[t] = 0.0f;
    __syncthreads();

    for (int i = gw; i < n; i += SPLIT * 8) {
        // stage Q row (128 floats = 32 lanes x float4)
        {
            float4 v = *(const float4*)&g_QKV[(s + i) * QKV_COLS + lane * 4];
            *(float4*)&sQ[w * KEY_DIM + lane * 4] = v;
        }
        __syncwarp();

        const ulonglong2* q4 = (const ulonglong2*)&sQ[w * KEY_DIM];
        float sc[(NGMAX + 31) / 32];
        float m = -INFINITY;
        int nj = 0;
        for (int j = lane; j < n; j += 32) {
            const ulonglong2* k4 = (const ulonglong2*)&sK[j * KPAD];
            ull a0 = 0, a1 = 0, a2v = 0, a3 = 0;
#pragma unroll 4
            for (int kk = 0; kk < KEY_DIM / 4; kk += 2) {   // 16 iters of 2x LDS.128 each side
                ulonglong2 qa = q4[kk], qb = q4[kk + 1];
                ulonglong2 ka = k4[kk], kb = k4[kk + 1];
                ffma2(a0,  qa.x, ka.x);
                ffma2(a1,  qa.y, ka.y);
                ffma2(a2v, qb.x, kb.x);
                ffma2(a3,  qb.y, kb.y);
            }
            float2 t2 = unpack2(addx2(addx2(a0, a1), addx2(a2v, a3)));
            float d = (t2.x + t2.y) * 0.0625f;       // / sqrt(256)
            sc[nj++] = d;
            m = fmaxf(m, d);
        }
#pragma unroll
        for (int o = 16; o > 0; o >>= 1) m = fmaxf(m, __shfl_xor_sync(0xffffffffu, m, o));
        float ssum = 0.0f;
        for (int q = 0; q < nj; q++) { sc[q] = __expf(sc[q] - m); ssum += sc[q]; }
#pragma unroll
        for (int o = 16; o > 0; o >>= 1) ssum += __shfl_xor_sync(0xffffffffu, ssum, o);
        const float inv = 1.0f / ssum;
        nj = 0;
        for (int j = lane; j < n; j += 32) wcol[w * NGMAX + j] += sc[nj++] * inv;
        __syncwarp();                                // protect sQ before next row
    }
    __syncthreads();

    // Reduce this CTA's 8 warp-partials, write the split-partial (fixed order)
    for (int j = tid; j < n; j += 256) {
        float t = 0.0f;
#pragma unroll
        for (int ww = 0; ww < 8; ww++) t += wcol[ww * NGMAX + j];
        g_wpart[(r * N_GRAPHS + g) * NGMAX + j] = t;
    }
}

// ---------------------------------------------------------------------------
// Kernel 4: final reduce + weighted V sum. One CTA (256 thr) per graph.
// ---------------------------------------------------------------------------
__global__ __launch_bounds__(256)
void attn_out_kernel(float* __restrict__ out) {
    __shared__ float colsum[NGMAX];

    const int g   = blockIdx.x;
    const int tid = threadIdx.x;

    int s = g_start[g];
    int n = g_end[g] - s;
    if (n <= 0) {
        out[g * N_FEATURES + tid] = 0.0f;
        return;
    }
    if (n > NGMAX) n = NGMAX;

    if (tid < NGMAX) {
        int j = tid;
        float t = 0.0f;
        if (j < n) {
#pragma unroll
            for (int r = 0; r < SPLIT; r++)
                t += g_wpart[(r * N_GRAPHS + g) * NGMAX + j];
        }
        colsum[j] = t;
    }
    __syncthreads();

    // Weighted sum of V rows; thread = feature (coalesced 1KB rows), 4-way MLP
    const int f = tid;
    const float* Vb = &g_QKV[(size_t)s * QKV_COLS + 2 * KEY_DIM + f];
    float a0 = 0.0f, a1 = 0.0f, a2 = 0.0f, a3 = 0.0f;
    int j = 0;
    for (; j + 3 < n; j += 4) {
        a0 += colsum[j + 0] * Vb[(size_t)(j + 0) * QKV_COLS];
        a1 += colsum[j + 1] * Vb[(size_t)(j + 1) * QKV_COLS];
        a2 += colsum[j + 2] * Vb[(size_t)(j + 2) * QKV_COLS];
        a3 += colsum[j + 3] * Vb[(size_t)(j + 3) * QKV_COLS];
    }
    for (; j < n; j++) a0 += colsum[j] * Vb[(size_t)j * QKV_COLS];
    out[g * N_FEATURES + f] = (a0 + a1) + (a2 + a3);
}

// ---------------------------------------------------------------------------
// Launch
// ---------------------------------------------------------------------------
extern "C" void kernel_launch(void* const* d_in, const int* in_sizes, int n_in,
                              void* d_out, int out_size) {
    const float* X  = (const float*)d_in[0];
    const void*  batch = d_in[1];
    const float* Wq = (const float*)d_in[2];
    const float* Wk = (const float*)d_in[3];
    const float* Wv = (const float*)d_in[4];
    float* out = (float*)d_out;

    cudaFuncSetAttribute(attn_score_kernel,
                         cudaFuncAttributeMaxDynamicSharedMemorySize,
                         SC_SMEM_BYTES);
    cudaFuncSetAttribute(qkv_gemm_kernel,
                         cudaFuncAttributeMaxDynamicSharedMemorySize,
                         GB_SMEM_BYTES);

    init_ranges_kernel<<<1, N_GRAPHS>>>();
    compute_ranges_kernel<<<(N_NODES + 255) / 256, 256>>>(batch);
    qkv_gemm_kernel<<<dim3(4, N_NODES / GB_M), 256, GB_SMEM_BYTES>>>(X, Wq, Wk, Wv);
    attn_score_kernel<<<dim3(SPLIT, N_GRAPHS), 256, SC_SMEM_BYTES>>>();
    attn_out_kernel<<<N_GRAPHS, 256>>>(out);
}

// round 11
// speedup vs baseline: 1.0031x; 1.0031x over previous
#include <cuda_runtime.h>
#include <cuda_bf16.h>
#include <math.h>
#include <limits.h>

// Problem constants (fixed by the reference)
#define N_NODES    12288
#define N_FEATURES 256
#define KEY_DIM    128
#define N_GRAPHS   192
#define QKV_COLS   512        // [Q(128) | K(128) | V(256)]

#define SPLIT 4               // row-split CTAs per graph for the score phase
#define NGMAX 128
#define KPAD  132             // 132*4B = 528B row stride: 16B-aligned, phase-conflict-free

typedef unsigned long long ull;

// Packed fp32x2 ops (Blackwell sm_103a; ptxas never emits FFMA2 from C++)
__device__ __forceinline__ void ffma2(ull& d, ull a, ull b) {
    asm("fma.rn.f32x2 %0, %1, %2, %0;" : "+l"(d) : "l"(a), "l"(b));
}
__device__ __forceinline__ ull pack2(float lo, float hi) {
    ull r; asm("mov.b64 %0, {%1, %2};" : "=l"(r) : "f"(lo), "f"(hi)); return r;
}
__device__ __forceinline__ float2 unpack2(ull v) {
    float2 r; asm("mov.b64 {%0, %1}, %2;" : "=f"(r.x), "=f"(r.y) : "l"(v)); return r;
}
__device__ __forceinline__ ull addx2(ull a, ull b) {
    ull r; asm("add.rn.f32x2 %0, %1, %2;" : "=l"(r) : "l"(a), "l"(b)); return r;
}

// Static device scratch (no allocs)
__device__ float g_QKV[N_NODES * QKV_COLS];              // 25.2 MB
__device__ float g_wpart[SPLIT * N_GRAPHS * NGMAX];      // 384 KB partial colsums
__device__ int   g_start[N_GRAPHS];
__device__ int   g_end[N_GRAPHS];

// ---------------------------------------------------------------------------
// Kernel 0: init per-graph ranges
// ---------------------------------------------------------------------------
__global__ void init_ranges_kernel() {
    int g = blockIdx.x * blockDim.x + threadIdx.x;
    if (g < N_GRAPHS) {
        g_start[g] = INT_MAX;
        g_end[g]   = 0;
    }
}

// ---------------------------------------------------------------------------
// Kernel 1: per-graph [start, end) from sorted batch (robust to int32/int64)
// ---------------------------------------------------------------------------
__global__ void compute_ranges_kernel(const void* __restrict__ batch) {
    int i = blockIdx.x * blockDim.x + threadIdx.x;
    if (i >= N_NODES) return;
    const long long* b64 = (const long long*)batch;
    long long probe = b64[N_NODES / 4];
    bool is32 = (probe < 0) || (probe >= (long long)N_GRAPHS);
    int g = is32 ? ((const int*)batch)[i] : (int)b64[i];
    if (g < 0 || g >= N_GRAPHS) return;   // defensive
    atomicMin(&g_start[g], i);
    atomicMax(&g_end[g], i + 1);
}

// ---------------------------------------------------------------------------
// Kernel 2: fused QKV projection GEMM, fp32x2 FMAs, double-buffered smem.
//   QKV[N, 512] = X[N, 256] @ [Wq | Wk | Wv]
// BM=64, BN=128, BK=32, 256 threads, 8x4 micro-tile as 4 row-pairs of FFMA2.
// Dynamic smem: 2 x (A 32x66 + B 32x128) = 49.7 KB, one sync per K-step.
// ---------------------------------------------------------------------------
#define GB_M 64
#define GB_N 128
#define GB_K 32
#define GB_MPAD 66     // even -> 8B-aligned row-pair loads
#define GB_A_FLOATS (GB_K * GB_MPAD)
#define GB_B_FLOATS (GB_K * GB_N)
#define GB_SMEM_BYTES (2 * (GB_A_FLOATS + GB_B_FLOATS) * 4)

__global__ __launch_bounds__(256, 2)
void qkv_gemm_kernel(const float* __restrict__ X,
                     const float* __restrict__ Wq,
                     const float* __restrict__ Wk,
                     const float* __restrict__ Wv) {
    extern __shared__ float gsm[];
    float* Abuf[2] = { gsm, gsm + GB_A_FLOATS };
    float* Bbuf[2] = { gsm + 2 * GB_A_FLOATS, gsm + 2 * GB_A_FLOATS + GB_B_FLOATS };

    const int bx = blockIdx.x;   // 0..3 weight slab
    const int by = blockIdx.y;   // 0..191

    const float* W;
    int ldw, ncol0;
    if (bx == 0)      { W = Wq; ldw = KEY_DIM;    ncol0 = 0;   }
    else if (bx == 1) { W = Wk; ldw = KEY_DIM;    ncol0 = 0;   }
    else              { W = Wv; ldw = N_FEATURES; ncol0 = (bx - 2) * 128; }

    const int tid  = threadIdx.x;
    const int ty   = tid >> 5;        // 0..7   -> row group (8 rows)
    const int tx   = tid & 31;        // 0..31  -> col group (4 cols)
    const int row0 = by * GB_M;

    // Per-thread load coordinates (fixed across tiles)
    const int ar0 = tid >> 3,          ac0 = (tid & 7) << 2;          // A elem 0
    const int ar1 = (tid + 256) >> 3,  ac1 = ((tid + 256) & 7) << 2;  // A elem 1
    int br[4], bc[4];
#pragma unroll
    for (int i = 0; i < 4; i++) {
        int t = tid + i * 256;
        br[i] = t >> 5; bc[i] = (t & 31) << 2;
    }

    float4 aR[2], bR[4];
    // Prologue: tile 0
    aR[0] = *(const float4*)&X[(row0 + ar0) * N_FEATURES + ac0];
    aR[1] = *(const float4*)&X[(row0 + ar1) * N_FEATURES + ac1];
#pragma unroll
    for (int i = 0; i < 4; i++)
        bR[i] = *(const float4*)&W[br[i] * ldw + ncol0 + bc[i]];
    {
        float* As = Abuf[0]; float* Bs = Bbuf[0];
        As[(ac0 + 0) * GB_MPAD + ar0] = aR[0].x;
        As[(ac0 + 1) * GB_MPAD + ar0] = aR[0].y;
        As[(ac0 + 2) * GB_MPAD + ar0] = aR[0].z;
        As[(ac0 + 3) * GB_MPAD + ar0] = aR[0].w;
        As[(ac1 + 0) * GB_MPAD + ar1] = aR[1].x;
        As[(ac1 + 1) * GB_MPAD + ar1] = aR[1].y;
        As[(ac1 + 2) * GB_MPAD + ar1] = aR[1].z;
        As[(ac1 + 3) * GB_MPAD + ar1] = aR[1].w;
#pragma unroll
        for (int i = 0; i < 4; i++)
            *(float4*)&Bs[br[i] * GB_N + bc[i]] = bR[i];
    }
    __syncthreads();

    ull acc2[4][4];
#pragma unroll
    for (int rp = 0; rp < 4; rp++)
#pragma unroll
        for (int c = 0; c < 4; c++) acc2[rp][c] = 0ull;

    const int NT = N_FEATURES / GB_K;   // 8 tiles
    for (int t8 = 0; t8 < NT; t8++) {
        const int cur = t8 & 1;
        float* Ac = Abuf[cur];
        float* Bc = Bbuf[cur];

        if (t8 + 1 < NT) {              // issue next-tile LDGs early
            int k0 = (t8 + 1) * GB_K;
            aR[0] = *(const float4*)&X[(row0 + ar0) * N_FEATURES + k0 + ac0];
            aR[1] = *(const float4*)&X[(row0 + ar1) * N_FEATURES + k0 + ac1];
#pragma unroll
            for (int i = 0; i < 4; i++)
                bR[i] = *(const float4*)&W[(k0 + br[i]) * ldw + ncol0 + bc[i]];
        }

#pragma unroll
        for (int k = 0; k < GB_K; k++) {
            const ull* arow = (const ull*)&Ac[k * GB_MPAD + ty * 8]; // broadcast LDS.64
            ull a2[4];
#pragma unroll
            for (int rp = 0; rp < 4; rp++) a2[rp] = arow[rp];
            float4 bv = *(const float4*)&Bc[k * GB_N + tx * 4];
            ull bd[4] = { pack2(bv.x, bv.x), pack2(bv.y, bv.y),
                          pack2(bv.z, bv.z), pack2(bv.w, bv.w) };
#pragma unroll
            for (int rp = 0; rp < 4; rp++)
#pragma unroll
                for (int c = 0; c < 4; c++) ffma2(acc2[rp][c], a2[rp], bd[c]);
        }

        if (t8 + 1 < NT) {
            float* An = Abuf[1 - cur];
            float* Bn = Bbuf[1 - cur];
            An[(ac0 + 0) * GB_MPAD + ar0] = aR[0].x;
            An[(ac0 + 1) * GB_MPAD + ar0] = aR[0].y;
            An[(ac0 + 2) * GB_MPAD + ar0] = aR[0].z;
            An[(ac0 + 3) * GB_MPAD + ar0] = aR[0].w;
            An[(ac1 + 0) * GB_MPAD + ar1] = aR[1].x;
            An[(ac1 + 1) * GB_MPAD + ar1] = aR[1].y;
            An[(ac1 + 2) * GB_MPAD + ar1] = aR[1].z;
            An[(ac1 + 3) * GB_MPAD + ar1] = aR[1].w;
#pragma unroll
            for (int i = 0; i < 4; i++)
                *(float4*)&Bn[br[i] * GB_N + bc[i]] = bR[i];
            __syncthreads();
        }
    }

    const int col0 = bx * 128 + tx * 4;
#pragma unroll
    for (int rp = 0; rp < 4; rp++) {
        float2 p0 = unpack2(acc2[rp][0]);
        float2 p1 = unpack2(acc2[rp][1]);
        float2 p2 = unpack2(acc2[rp][2]);
        float2 p3 = unpack2(acc2[rp][3]);
        int re = row0 + ty * 8 + 2 * rp;
        *(float4*)&g_QKV[re * QKV_COLS + col0]       = make_float4(p0.x, p1.x, p2.x, p3.x);
        *(float4*)&g_QKV[(re + 1) * QKV_COLS + col0] = make_float4(p0.y, p1.y, p2.y, p3.y);
    }
}

// ---------------------------------------------------------------------------
// Kernel 3: score phase, row-split across SPLIT CTAs per graph.
// __launch_bounds__(256, 2): cap regs at 128 so 2 CTAs/SM are resident.
// LDS.128 dot loads (ulonglong2), moderate unroll to keep live regs low.
// ---------------------------------------------------------------------------
#define SC_SMEM_FLOATS (NGMAX * KPAD + 8 * NGMAX + 8 * KEY_DIM)
#define SC_SMEM_BYTES  (SC_SMEM_FLOATS * 4)

__global__ __launch_bounds__(256, 2)
void attn_score_kernel() {
    extern __shared__ float sm[];
    float* sK   = sm;                         // NGMAX * KPAD (16B-aligned rows)
    float* wcol = sK + NGMAX * KPAD;          // 8 * NGMAX (per-warp partials)
    float* sQ   = wcol + 8 * NGMAX;           // 8 * 128

    const int r    = blockIdx.x;              // 0..SPLIT-1
    const int g    = blockIdx.y;              // 0..191
    const int tid  = threadIdx.x;
    const int w    = tid >> 5;
    const int lane = tid & 31;
    const int gw   = r * 8 + w;               // 0..31 global warp within graph

    int s = g_start[g];
    int n = g_end[g] - s;
    if (n <= 0) return;                       // out kernel writes zeros
    if (n > NGMAX) n = NGMAX;                 // unreachable (mean 64, max ~95)

    // Stage K rows: float4 gmem reads, float4 smem stores (rows 16B-aligned)
    for (int t = tid; t < n * (KEY_DIM / 4); t += 256) {
        int j = t >> 5;
        int k = (t & 31) << 2;
        float4 v = *(const float4*)&g_QKV[(s + j) * QKV_COLS + KEY_DIM + k];
        *(float4*)&sK[j * KPAD + k] = v;
    }
    for (int t = tid; t < 8 * NGMAX; t += 256) wcol[t] = 0.0f;
    __syncthreads();

    for (int i = gw; i < n; i += SPLIT * 8) {
        // stage Q row (128 floats = 32 lanes x float4)
        {
            float4 v = *(const float4*)&g_QKV[(s + i) * QKV_COLS + lane * 4];
            *(float4*)&sQ[w * KEY_DIM + lane * 4] = v;
        }
        __syncwarp();

        const ulonglong2* q4 = (const ulonglong2*)&sQ[w * KEY_DIM];
        float sc[(NGMAX + 31) / 32];
        float m = -INFINITY;
        int nj = 0;
        for (int j = lane; j < n; j += 32) {
            const ulonglong2* k4 = (const ulonglong2*)&sK[j * KPAD];
            ull a0 = 0, a1 = 0, a2v = 0, a3 = 0;
#pragma unroll 4
            for (int kk = 0; kk < KEY_DIM / 4; kk += 2) {   // 16 iters of 2x LDS.128 each side
                ulonglong2 qa = q4[kk], qb = q4[kk + 1];
                ulonglong2 ka = k4[kk], kb = k4[kk + 1];
                ffma2(a0,  qa.x, ka.x);
                ffma2(a1,  qa.y, ka.y);
                ffma2(a2v, qb.x, kb.x);
                ffma2(a3,  qb.y, kb.y);
            }
            float2 t2 = unpack2(addx2(addx2(a0, a1), addx2(a2v, a3)));
            float d = (t2.x + t2.y) * 0.0625f;       // / sqrt(256)
            sc[nj++] = d;
            m = fmaxf(m, d);
        }
#pragma unroll
        for (int o = 16; o > 0; o >>= 1) m = fmaxf(m, __shfl_xor_sync(0xffffffffu, m, o));
        float ssum = 0.0f;
        for (int q = 0; q < nj; q++) { sc[q] = __expf(sc[q] - m); ssum += sc[q]; }
#pragma unroll
        for (int o = 16; o > 0; o >>= 1) ssum += __shfl_xor_sync(0xffffffffu, ssum, o);
        const float inv = 1.0f / ssum;
        nj = 0;
        for (int j = lane; j < n; j += 32) wcol[w * NGMAX + j] += sc[nj++] * inv;
        __syncwarp();                                // protect sQ before next row
    }
    __syncthreads();

    // Reduce this CTA's 8 warp-partials, write the split-partial (fixed order)
    for (int j = tid; j < n; j += 256) {
        float t = 0.0f;
#pragma unroll
        for (int ww = 0; ww < 8; ww++) t += wcol[ww * NGMAX + j];
        g_wpart[(r * N_GRAPHS + g) * NGMAX + j] = t;
    }
}

// ---------------------------------------------------------------------------
// Kernel 4: final reduce + weighted V sum. One CTA (256 thr) per graph.
// ---------------------------------------------------------------------------
__global__ __launch_bounds__(256)
void attn_out_kernel(float* __restrict__ out) {
    __shared__ float colsum[NGMAX];

    const int g   = blockIdx.x;
    const int tid = threadIdx.x;

    int s = g_start[g];
    int n = g_end[g] - s;
    if (n <= 0) {
        out[g * N_FEATURES + tid] = 0.0f;
        return;
    }
    if (n > NGMAX) n = NGMAX;

    if (tid < NGMAX) {
        int j = tid;
        float t = 0.0f;
        if (j < n) {
#pragma unroll
            for (int r = 0; r < SPLIT; r++)
                t += g_wpart[(r * N_GRAPHS + g) * NGMAX + j];
        }
        colsum[j] = t;
    }
    __syncthreads();

    // Weighted sum of V rows; thread = feature (coalesced 1KB rows), 4-way MLP
    const int f = tid;
    const float* Vb = &g_QKV[(size_t)s * QKV_COLS + 2 * KEY_DIM + f];
    float a0 = 0.0f, a1 = 0.0f, a2 = 0.0f, a3 = 0.0f;
    int j = 0;
    for (; j + 3 < n; j += 4) {
        a0 += colsum[j + 0] * Vb[(size_t)(j + 0) * QKV_COLS];
        a1 += colsum[j + 1] * Vb[(size_t)(j + 1) * QKV_COLS];
        a2 += colsum[j + 2] * Vb[(size_t)(j + 2) * QKV_COLS];
        a3 += colsum[j + 3] * Vb[(size_t)(j + 3) * QKV_COLS];
    }
    for (; j < n; j++) a0 += colsum[j] * Vb[(size_t)j * QKV_COLS];
    out[g * N_FEATURES + f] = (a0 + a1) + (a2 + a3);
}

// ---------------------------------------------------------------------------
// Launch
// ---------------------------------------------------------------------------
extern "C" void kernel_launch(void* const* d_in, const int* in_sizes, int n_in,
                              void* d_out, int out_size) {
    const float* X  = (const float*)d_in[0];
    const void*  batch = d_in[1];
    const float* Wq = (const float*)d_in[2];
    const float* Wk = (const float*)d_in[3];
    const float* Wv = (const float*)d_in[4];
    float* out = (float*)d_out;

    cudaFuncSetAttribute(attn_score_kernel,
                         cudaFuncAttributeMaxDynamicSharedMemorySize,
                         SC_SMEM_BYTES);
    cudaFuncSetAttribute(qkv_gemm_kernel,
                         cudaFuncAttributeMaxDynamicSharedMemorySize,
                         GB_SMEM_BYTES);

    init_ranges_kernel<<<1, N_GRAPHS>>>();
    compute_ranges_kernel<<<(N_NODES + 255) / 256, 256>>>(batch);
    qkv_gemm_kernel<<<dim3(4, N_NODES / GB_M), 256, GB_SMEM_BYTES>>>(X, Wq, Wk, Wv);
    attn_score_kernel<<<dim3(SPLIT, N_GRAPHS), 256, SC_SMEM_BYTES>>>();
    attn_out_kernel<<<N_GRAPHS, 256>>>(out);
}

// round 12
// speedup vs baseline: 1.1508x; 1.1472x over previous
#include <cuda_runtime.h>
#include <cuda_bf16.h>
#include <math.h>
#include <limits.h>

// Problem constants (fixed by the reference)
#define N_NODES    12288
#define N_FEATURES 256
#define KEY_DIM    128
#define N_GRAPHS   192
#define QKV_COLS   512        // [Q(128) | K(128) | V(256)]

#define SPLIT 4               // row-split CTAs per graph for the score phase
#define NGMAX 128
#define KPAD  132             // 132*4B = 528B row stride: 16B-aligned, phase-conflict-free

typedef unsigned long long ull;

// Packed fp32x2 ops (Blackwell sm_103a; ptxas never emits FFMA2 from C++)
__device__ __forceinline__ void ffma2(ull& d, ull a, ull b) {
    asm("fma.rn.f32x2 %0, %1, %2, %0;" : "+l"(d) : "l"(a), "l"(b));
}
__device__ __forceinline__ ull pack2(float lo, float hi) {
    ull r; asm("mov.b64 %0, {%1, %2};" : "=l"(r) : "f"(lo), "f"(hi)); return r;
}
__device__ __forceinline__ float2 unpack2(ull v) {
    float2 r; asm("mov.b64 {%0, %1}, %2;" : "=f"(r.x), "=f"(r.y) : "l"(v)); return r;
}
__device__ __forceinline__ ull addx2(ull a, ull b) {
    ull r; asm("add.rn.f32x2 %0, %1, %2;" : "=l"(r) : "l"(a), "l"(b)); return r;
}

// Static device scratch (no allocs)
__device__ float g_QKV[N_NODES * QKV_COLS];              // 25.2 MB
__device__ float g_wpart[SPLIT * N_GRAPHS * NGMAX];      // 384 KB partial colsums
__device__ int   g_start[N_GRAPHS];
__device__ int   g_end[N_GRAPHS];

// ---------------------------------------------------------------------------
// Kernel 0: init per-graph ranges
// ---------------------------------------------------------------------------
__global__ void init_ranges_kernel() {
    int g = blockIdx.x * blockDim.x + threadIdx.x;
    if (g < N_GRAPHS) {
        g_start[g] = INT_MAX;
        g_end[g]   = 0;
    }
}

// ---------------------------------------------------------------------------
// Kernel 1: per-graph [start, end) from sorted batch (robust to int32/int64)
// ---------------------------------------------------------------------------
__global__ void compute_ranges_kernel(const void* __restrict__ batch) {
    int i = blockIdx.x * blockDim.x + threadIdx.x;
    if (i >= N_NODES) return;
    const long long* b64 = (const long long*)batch;
    long long probe = b64[N_NODES / 4];
    bool is32 = (probe < 0) || (probe >= (long long)N_GRAPHS);
    int g = is32 ? ((const int*)batch)[i] : (int)b64[i];
    if (g < 0 || g >= N_GRAPHS) return;   // defensive
    atomicMin(&g_start[g], i);
    atomicMax(&g_end[g], i + 1);
}

// ---------------------------------------------------------------------------
// Kernel 2: fused QKV projection GEMM (round-9 known-good version).
//   QKV[N, 512] = X[N, 256] @ [Wq | Wk | Wv]
// BM=64, BN=128, BK=32, 256 threads, 8x4 micro-tile as 4 row-pairs of FFMA2.
// ---------------------------------------------------------------------------
#define GB_M 64
#define GB_N 128
#define GB_K 32
#define GB_MPAD 66     // even -> 8B-aligned row-pair loads

__global__ __launch_bounds__(256)
void qkv_gemm_kernel(const float* __restrict__ X,
                     const float* __restrict__ Wq,
                     const float* __restrict__ Wk,
                     const float* __restrict__ Wv) {
    __shared__ float As[GB_K * GB_MPAD];   // transposed A tile (k-major), padded
    __shared__ float Bs[GB_K * GB_N];

    const int bx = blockIdx.x;   // 0..3 weight slab
    const int by = blockIdx.y;   // 0..191

    const float* W;
    int ldw, ncol0;
    if (bx == 0)      { W = Wq; ldw = KEY_DIM;    ncol0 = 0;   }
    else if (bx == 1) { W = Wk; ldw = KEY_DIM;    ncol0 = 0;   }
    else              { W = Wv; ldw = N_FEATURES; ncol0 = (bx - 2) * 128; }

    const int tid  = threadIdx.x;
    const int ty   = tid >> 5;        // 0..7   -> row group (8 rows)
    const int tx   = tid & 31;        // 0..31  -> col group (4 cols)
    const int row0 = by * GB_M;

    ull acc2[4][4];                   // [row-pair][col]
#pragma unroll
    for (int rp = 0; rp < 4; rp++)
#pragma unroll
        for (int c = 0; c < 4; c++) acc2[rp][c] = 0ull;

    for (int k0 = 0; k0 < N_FEATURES; k0 += GB_K) {
#pragma unroll
        for (int t = tid; t < (GB_M * GB_K) / 4; t += 256) {
            int r = t >> 3;
            int c = (t & 7) << 2;
            float4 v = *(const float4*)&X[(row0 + r) * N_FEATURES + k0 + c];
            As[(c + 0) * GB_MPAD + r] = v.x;
            As[(c + 1) * GB_MPAD + r] = v.y;
            As[(c + 2) * GB_MPAD + r] = v.z;
            As[(c + 3) * GB_MPAD + r] = v.w;
        }
#pragma unroll
        for (int t = tid; t < (GB_K * GB_N) / 4; t += 256) {
            int r = t >> 5;
            int c = (t & 31) << 2;
            float4 v = *(const float4*)&W[(k0 + r) * ldw + ncol0 + c];
            *(float4*)&Bs[r * GB_N + c] = v;
        }
        __syncthreads();

#pragma unroll
        for (int k = 0; k < GB_K; k++) {
            const ull* arow = (const ull*)&As[k * GB_MPAD + ty * 8]; // broadcast LDS.64
            ull a2[4];
#pragma unroll
            for (int rp = 0; rp < 4; rp++) a2[rp] = arow[rp];
            float4 bv = *(const float4*)&Bs[k * GB_N + tx * 4];
            ull bd[4] = { pack2(bv.x, bv.x), pack2(bv.y, bv.y),
                          pack2(bv.z, bv.z), pack2(bv.w, bv.w) };
#pragma unroll
            for (int rp = 0; rp < 4; rp++)
#pragma unroll
                for (int c = 0; c < 4; c++) ffma2(acc2[rp][c], a2[rp], bd[c]);
        }
        __syncthreads();
    }

    const int col0 = bx * 128 + tx * 4;
#pragma unroll
    for (int rp = 0; rp < 4; rp++) {
        float2 p0 = unpack2(acc2[rp][0]);
        float2 p1 = unpack2(acc2[rp][1]);
        float2 p2 = unpack2(acc2[rp][2]);
        float2 p3 = unpack2(acc2[rp][3]);
        int re = row0 + ty * 8 + 2 * rp;
        *(float4*)&g_QKV[re * QKV_COLS + col0]       = make_float4(p0.x, p1.x, p2.x, p3.x);
        *(float4*)&g_QKV[(re + 1) * QKV_COLS + col0] = make_float4(p0.y, p1.y, p2.y, p3.y);
    }
}

// ---------------------------------------------------------------------------
// Kernel 3: score phase, row-split across SPLIT CTAs per graph.
// __launch_bounds__(256, 3): 3 CTAs/SM (smem 75.8KB x3 = 227KB fits; regs<=84).
// Per-warp colsum kept in REGISTERS (lane owns j = lane + 32q), one smem
// write at the end -> removes the smem RMW stream from the hot loop.
// ---------------------------------------------------------------------------
#define SC_SMEM_FLOATS (NGMAX * KPAD + 8 * NGMAX + 8 * KEY_DIM)
#define SC_SMEM_BYTES  (SC_SMEM_FLOATS * 4)

__global__ __launch_bounds__(256, 3)
void attn_score_kernel() {
    extern __shared__ float sm[];
    float* sK   = sm;                         // NGMAX * KPAD (16B-aligned rows)
    float* wcol = sK + NGMAX * KPAD;          // 8 * NGMAX (per-warp partials, final)
    float* sQ   = wcol + 8 * NGMAX;           // 8 * 128

    const int r    = blockIdx.x;              // 0..SPLIT-1
    const int g    = blockIdx.y;              // 0..191
    const int tid  = threadIdx.x;
    const int w    = tid >> 5;
    const int lane = tid & 31;
    const int gw   = r * 8 + w;               // 0..31 global warp within graph

    int s = g_start[g];
    int n = g_end[g] - s;
    if (n <= 0) return;                       // out kernel writes zeros
    if (n > NGMAX) n = NGMAX;                 // unreachable (mean 64, max ~95)

    // Stage K rows: float4 gmem reads, float4 smem stores (rows 16B-aligned)
    for (int t = tid; t < n * (KEY_DIM / 4); t += 256) {
        int j = t >> 5;
        int k = (t & 31) << 2;
        float4 v = *(const float4*)&g_QKV[(s + j) * QKV_COLS + KEY_DIM + k];
        *(float4*)&sK[j * KPAD + k] = v;
    }
    __syncthreads();

    // Register-resident per-warp colsum: lane owns j = lane, lane+32, ...
    float wsum[4] = {0.0f, 0.0f, 0.0f, 0.0f};

    for (int i = gw; i < n; i += SPLIT * 8) {
        // stage Q row (128 floats = 32 lanes x float4)
        {
            float4 v = *(const float4*)&g_QKV[(s + i) * QKV_COLS + lane * 4];
            *(float4*)&sQ[w * KEY_DIM + lane * 4] = v;
        }
        __syncwarp();

        const ulonglong2* q4 = (const ulonglong2*)&sQ[w * KEY_DIM];
        float sc[4];
        float m = -INFINITY;
        int nj = 0;
        for (int j = lane; j < n; j += 32) {
            const ulonglong2* k4 = (const ulonglong2*)&sK[j * KPAD];
            ull a0 = 0, a1 = 0, a2v = 0, a3 = 0;
#pragma unroll 4
            for (int kk = 0; kk < KEY_DIM / 4; kk += 2) {   // 2x LDS.128 each side
                ulonglong2 qa = q4[kk], qb = q4[kk + 1];
                ulonglong2 ka = k4[kk], kb = k4[kk + 1];
                ffma2(a0,  qa.x, ka.x);
                ffma2(a1,  qa.y, ka.y);
                ffma2(a2v, qb.x, kb.x);
                ffma2(a3,  qb.y, kb.y);
            }
            float2 t2 = unpack2(addx2(addx2(a0, a1), addx2(a2v, a3)));
            float d = (t2.x + t2.y) * 0.0625f;       // / sqrt(256)
            sc[nj++] = d;
            m = fmaxf(m, d);
        }
#pragma unroll
        for (int o = 16; o > 0; o >>= 1) m = fmaxf(m, __shfl_xor_sync(0xffffffffu, m, o));
        float ssum = 0.0f;
#pragma unroll
        for (int q = 0; q < 4; q++)
            if (q < nj) { sc[q] = __expf(sc[q] - m); ssum += sc[q]; }
#pragma unroll
        for (int o = 16; o > 0; o >>= 1) ssum += __shfl_xor_sync(0xffffffffu, ssum, o);
        const float inv = 1.0f / ssum;
#pragma unroll
        for (int q = 0; q < 4; q++)
            if (q < nj) wsum[q] += sc[q] * inv;
        __syncwarp();                                // protect sQ before next row
    }

    // Write per-warp partials once, then reduce across warps (fixed order)
#pragma unroll
    for (int q = 0; q < 4; q++) {
        int j = lane + 32 * q;
        if (j < NGMAX) wcol[w * NGMAX + j] = wsum[q];
    }
    __syncthreads();

    for (int j = tid; j < n; j += 256) {
        float t = 0.0f;
#pragma unroll
        for (int ww = 0; ww < 8; ww++) t += wcol[ww * NGMAX + j];
        g_wpart[(r * N_GRAPHS + g) * NGMAX + j] = t;
    }
}

// ---------------------------------------------------------------------------
// Kernel 4: final reduce + weighted V sum.
// Grid (2, N_GRAPHS), 128 threads: CTA (fz, g) handles features
// [fz*128, fz*128+128). Doubles CTA supply for this latency-bound sweep.
// ---------------------------------------------------------------------------
__global__ __launch_bounds__(128)
void attn_out_kernel(float* __restrict__ out) {
    __shared__ float colsum[NGMAX];

    const int fz  = blockIdx.x;               // 0..1 feature half
    const int g   = blockIdx.y;
    const int tid = threadIdx.x;
    const int f   = fz * 128 + tid;

    int s = g_start[g];
    int n = g_end[g] - s;
    if (n <= 0) {
        out[g * N_FEATURES + f] = 0.0f;
        return;
    }
    if (n > NGMAX) n = NGMAX;

    {
        int j = tid;                           // 128 threads cover NGMAX
        float t = 0.0f;
        if (j < n) {
#pragma unroll
            for (int r = 0; r < SPLIT; r++)
                t += g_wpart[(r * N_GRAPHS + g) * NGMAX + j];
        }
        colsum[j] = t;
    }
    __syncthreads();

    // Weighted sum of V rows; thread = feature (coalesced), 4-way MLP
    const float* Vb = &g_QKV[(size_t)s * QKV_COLS + 2 * KEY_DIM + f];
    float a0 = 0.0f, a1 = 0.0f, a2 = 0.0f, a3 = 0.0f;
    int j = 0;
    for (; j + 3 < n; j += 4) {
        a0 += colsum[j + 0] * Vb[(size_t)(j + 0) * QKV_COLS];
        a1 += colsum[j + 1] * Vb[(size_t)(j + 1) * QKV_COLS];
        a2 += colsum[j + 2] * Vb[(size_t)(j + 2) * QKV_COLS];
        a3 += colsum[j + 3] * Vb[(size_t)(j + 3) * QKV_COLS];
    }
    for (; j < n; j++) a0 += colsum[j] * Vb[(size_t)j * QKV_COLS];
    out[g * N_FEATURES + f] = (a0 + a1) + (a2 + a3);
}

// ---------------------------------------------------------------------------
// Launch
// ---------------------------------------------------------------------------
extern "C" void kernel_launch(void* const* d_in, const int* in_sizes, int n_in,
                              void* d_out, int out_size) {
    const float* X  = (const float*)d_in[0];
    const void*  batch = d_in[1];
    const float* Wq = (const float*)d_in[2];
    const float* Wk = (const float*)d_in[3];
    const float* Wv = (const float*)d_in[4];
    float* out = (float*)d_out;

    cudaFuncSetAttribute(attn_score_kernel,
                         cudaFuncAttributeMaxDynamicSharedMemorySize,
                         SC_SMEM_BYTES);

    init_ranges_kernel<<<1, N_GRAPHS>>>();
    compute_ranges_kernel<<<(N_NODES + 255) / 256, 256>>>(batch);
    qkv_gemm_kernel<<<dim3(4, N_NODES / GB_M), 256>>>(X, Wq, Wk, Wv);
    attn_score_kernel<<<dim3(SPLIT, N_GRAPHS), 256, SC_SMEM_BYTES>>>();
    attn_out_kernel<<<dim3(2, N_GRAPHS), 128>>>(out);
}